// round 6
// baseline (speedup 1.0000x reference)
#include <cuda_runtime.h>
#include <cstdint>

typedef unsigned long long u64;

#define BATCH 16
#define CHAN  256
#define H     64
#define W     64
#define HW    (H * W)
#define MAXD  4
#define PATCH 9

#define CC      4                  // channels per pipeline stage
#define NCHUNK  (CHAN / CC)        // 64
#define STAGES  3
#define YROWS   10                 // 2 + 2*MAXD
#define YPITCH  72                 // 4 pad + 64 + 4 pad
#define XROW    64
#define XS      (CC * 2 * XROW)    // 512 floats
#define YCH     (YROWS * YPITCH)   // 720 floats per channel
#define BUFF    (XS + CC * YCH)    // 3392 floats per stage
#define NELEM   768                // 128 x + 640 y 16B-units per chunk

__device__ __forceinline__ int swz(int u) { return u ^ ((u >> 3) & 1); }

__device__ __forceinline__ u64 pack2(float lo, float hi) {
    u64 d; asm("mov.b64 %0, {%1,%2};" : "=l"(d) : "f"(lo), "f"(hi)); return d;
}
__device__ __forceinline__ void unpack2(u64 v, float &lo, float &hi) {
    asm("mov.b64 {%0,%1}, %2;" : "=f"(lo), "=f"(hi) : "l"(v));
}
__device__ __forceinline__ void ffma2(u64 &d, u64 a, u64 b) {
    asm("fma.rn.f32x2 %0, %1, %2, %0;" : "+l"(d) : "l"(a), "l"(b));
}

// Block: (b, i0) tile of 2 rows. 9 warps, warp = di.
// lane: h = lane>>4 (channel half), il = (lane>>3)&1 (row), jseg = lane&7.
// Thread computes 8 px * 9 dj partial sums over its channel half; halves are
// combined with a shfl_xor(16) butterfly in the epilogue.
__global__ __launch_bounds__(288, 2)
void corr_kernel(const float* __restrict__ x,
                 const float* __restrict__ y,
                 float* __restrict__ out)
{
    __shared__ float smem[STAGES][BUFF];

    const int tid  = threadIdx.x;
    const int b    = blockIdx.x >> 5;
    const int i0   = (blockIdx.x & 31) * 2;
    const int di   = tid >> 5;
    const int lane = tid & 31;
    const int h    = lane >> 4;
    const int il   = (lane >> 3) & 1;
    const int jseg = lane & 7;
    const int j0   = jseg * 8;
    const int i    = i0 + il;
    const int ch0  = 2 * h;

    // ---- zero static y pads (units 0 and 17 of each padded row, all stages) ----
    for (int z = tid; z < STAGES * CC * YROWS * 8; z += 288) {
        int st  = z / (CC * YROWS * 8);
        int r1  = z - st * (CC * YROWS * 8);
        int ch  = r1 / (YROWS * 8);
        int r2  = r1 - ch * (YROWS * 8);
        int row = r2 >> 3;
        int p   = r2 & 7;
        int col = (p < 4) ? p : (64 + p);
        smem[st][XS + ch * YCH + row * YPITCH + col] = 0.f;
    }

    // ---- cp.async fill slots: 768 = 192*3 + 96*2 ----
    const int nslot = (tid < 192) ? 3 : 2;
    uint32_t     s_off[3];
    const float* g_ptr[3];
    uint32_t     s_sz[3];
    {
        const float* xb = x + ((size_t)b * CHAN) * HW + (size_t)i0 * W;
        const float* yb = y + ((size_t)b * CHAN) * HW;
        #pragma unroll
        for (int s = 0; s < 3; s++) {
            int e = tid + s * 288;
            if (e >= NELEM) e = 0;               // unreachable (exact fit), safety
            if (e < 128) {                       // x unit
                int ch = e >> 5, r = (e >> 4) & 1, u = e & 15;
                s_off[s] = (uint32_t)((ch * (2 * XROW) + r * XROW + swz(u) * 4) * 4);
                g_ptr[s] = xb + ch * HW + r * W + u * 4;
                s_sz[s]  = 16u;
            } else {                             // y interior unit (1..16)
                int e2 = e - 128;
                int ch = e2 / 160, rem = e2 - ch * 160;
                int row = rem >> 4, ui = (rem & 15) + 1;
                int yr = i0 - MAXD + row;
                bool v = (yr >= 0) && (yr < H);
                s_off[s] = (uint32_t)((XS + ch * YCH + row * YPITCH + swz(ui) * 4) * 4);
                g_ptr[s] = yb + ch * HW + (v ? yr : 0) * W + (ui - 1) * 4;
                s_sz[s]  = v ? 16u : 0u;         // 0 -> zero-fill
            }
        }
    }

    const uint32_t sm0 = (uint32_t)__cvta_generic_to_shared(&smem[0][0]);
    auto do_fill = [&](int st) {
        uint32_t base = sm0 + (uint32_t)st * (BUFF * 4);
        #pragma unroll
        for (int s = 0; s < 3; s++) {
            if (s < nslot) {
                asm volatile("cp.async.cg.shared.global [%0], [%1], 16, %2;"
                             :: "r"(base + s_off[s]), "l"(g_ptr[s]), "r"(s_sz[s]));
                g_ptr[s] += CC * HW;
            }
        }
    };

    // ---- per-thread LDS offsets (float indices within a stage buffer) ----
    int xo[2][2], yo[2][4];
    #pragma unroll
    for (int cc = 0; cc < 2; cc++) {
        int ch = ch0 + cc;
        #pragma unroll
        for (int k2 = 0; k2 < 2; k2++)
            xo[cc][k2] = ch * (2 * XROW) + il * XROW + swz(2 * jseg + k2) * 4;
        #pragma unroll
        for (int k4 = 0; k4 < 4; k4++)
            yo[cc][k4] = XS + ch * YCH + (il + di) * YPITCH + swz(2 * jseg + k4) * 4;
    }

    // ---- accumulators: 20 + 12 u64 + 8 f32 ----
    u64 accE[5][4], accO[4][3];
    float aS0[4], aS7[4];
    #pragma unroll
    for (int e = 0; e < 5; e++)
        #pragma unroll
        for (int t = 0; t < 4; t++) accE[e][t] = 0ull;
    #pragma unroll
    for (int o = 0; o < 4; o++) {
        aS0[o] = 0.f; aS7[o] = 0.f;
        #pragma unroll
        for (int s = 0; s < 3; s++) accO[o][s] = 0ull;
    }

    do_fill(0);
    asm volatile("cp.async.commit_group;" ::: "memory");
    do_fill(1);
    asm volatile("cp.async.commit_group;" ::: "memory");

    #pragma unroll 1
    for (int k = 0; k < NCHUNK; k++) {
        asm volatile("cp.async.wait_group 1;" ::: "memory");
        __syncthreads();                         // publishes chunk k + pads; fences refill target
        if (k + 2 < NCHUNK) do_fill((k + 2) % STAGES);
        asm volatile("cp.async.commit_group;" ::: "memory");

        const float* B = &smem[k % STAGES][0];
        #pragma unroll
        for (int cc = 0; cc < 2; cc++) {
            float4 x0 = *reinterpret_cast<const float4*>(B + xo[cc][0]);
            float4 x1 = *reinterpret_cast<const float4*>(B + xo[cc][1]);
            float4 ya = *reinterpret_cast<const float4*>(B + yo[cc][0]);
            float4 yb = *reinterpret_cast<const float4*>(B + yo[cc][1]);
            float4 yc = *reinterpret_cast<const float4*>(B + yo[cc][2]);
            float4 yd = *reinterpret_cast<const float4*>(B + yo[cc][3]);

            u64 Pm[8] = { pack2(ya.x, ya.y), pack2(ya.z, ya.w),
                          pack2(yb.x, yb.y), pack2(yb.z, yb.w),
                          pack2(yc.x, yc.y), pack2(yc.z, yc.w),
                          pack2(yd.x, yd.y), pack2(yd.z, yd.w) };
            u64 XE[4] = { pack2(x0.x, x0.y), pack2(x0.z, x0.w),
                          pack2(x1.x, x1.y), pack2(x1.z, x1.w) };
            u64 XO[3] = { pack2(x0.y, x0.z), pack2(x0.w, x1.x), pack2(x1.y, x1.z) };

            // even dj=2e: px pair (2t,2t+1): q pair index t+e
            #pragma unroll
            for (int e = 0; e < 5; e++)
                #pragma unroll
                for (int t = 0; t < 4; t++) ffma2(accE[e][t], XE[t], Pm[t + e]);
            // odd dj=2o+1: px pair (2s+1,2s+2): q pair index s+o+1
            #pragma unroll
            for (int o = 0; o < 4; o++)
                #pragma unroll
                for (int s = 0; s < 3; s++) ffma2(accO[o][s], XO[s], Pm[s + o + 1]);
            // odd dj edges: px0 uses q[2o+1], px7 uses q[2o+8]
            aS0[0] = fmaf(x0.x, ya.y, aS0[0]);
            aS0[1] = fmaf(x0.x, ya.w, aS0[1]);
            aS0[2] = fmaf(x0.x, yb.y, aS0[2]);
            aS0[3] = fmaf(x0.x, yb.w, aS0[3]);
            aS7[0] = fmaf(x1.w, yc.x, aS7[0]);
            aS7[1] = fmaf(x1.w, yc.z, aS7[1]);
            aS7[2] = fmaf(x1.w, yd.x, aS7[2]);
            aS7[3] = fmaf(x1.w, yd.z, aS7[3]);
        }
    }

    // ---- epilogue: butterfly-sum channel halves, scale, store ----
    const float inv = 1.0f / (float)CHAN;
    float* ob = out + (((size_t)b * (PATCH * PATCH) + (size_t)di * PATCH) * H + i) * W + j0 + 4 * h;
    #pragma unroll
    for (int dj = 0; dj < PATCH; dj++) {
        float v[8];
        if ((dj & 1) == 0) {
            const int e = dj >> 1;
            #pragma unroll
            for (int t = 0; t < 4; t++) unpack2(accE[e][t], v[2 * t], v[2 * t + 1]);
        } else {
            const int o = dj >> 1;
            v[0] = aS0[o];
            unpack2(accO[o][0], v[1], v[2]);
            unpack2(accO[o][1], v[3], v[4]);
            unpack2(accO[o][2], v[5], v[6]);
            v[7] = aS7[o];
        }
        #pragma unroll
        for (int m = 0; m < 8; m++) v[m] += __shfl_xor_sync(0xffffffffu, v[m], 16);
        float4 lo = make_float4(v[0], v[1], v[2], v[3]);
        float4 hi = make_float4(v[4], v[5], v[6], v[7]);
        float4 st = h ? hi : lo;
        st.x *= inv; st.y *= inv; st.z *= inv; st.w *= inv;
        *reinterpret_cast<float4*>(ob) = st;
        ob += HW;
    }
}

extern "C" void kernel_launch(void* const* d_in, const int* in_sizes, int n_in,
                              void* d_out, int out_size)
{
    const float* x = (const float*)d_in[0];
    const float* y = (const float*)d_in[1];
    float* out = (float*)d_out;
    dim3 grid(BATCH * 32);     // 512 blocks
    dim3 block(32 * PATCH);    // 288 threads = 9 warps
    corr_kernel<<<grid, block>>>(x, y, out);
}

// round 8
// speedup vs baseline: 1.2077x; 1.2077x over previous
#include <cuda_runtime.h>
#include <cstdint>

typedef unsigned long long u64;

#define BATCH 16
#define CHAN  256
#define H     64
#define W     64
#define HW    (H * W)
#define MAXD  4
#define PATCH 9
#define ITILE 4

#define CC      4                  // channels per pipeline stage
#define NCHUNK  (CHAN / CC)        // 64
#define STAGES  3
#define YROWS   (ITILE + 2*MAXD)   // 12
#define YPITCH  72                 // 4 pad + 64 + 4 pad (18 units)
#define XCH     (ITILE * W)        // 256 floats per channel
#define XS      (CC * XCH)         // 1024 floats
#define YCH     (YROWS * YPITCH)   // 864 floats per channel
#define BUFF    (XS + CC * YCH)    // 4480 floats per stage
#define NELEM   1024               // 256 x-units + 768 y-units per chunk

__device__ __forceinline__ int swz(int u) { return u ^ ((u >> 3) & 1); }

__device__ __forceinline__ u64 pack2(float lo, float hi) {
    u64 d; asm("mov.b64 %0, {%1,%2};" : "=l"(d) : "f"(lo), "f"(hi)); return d;
}
__device__ __forceinline__ void unpack2(u64 v, float &lo, float &hi) {
    asm("mov.b64 {%0,%1}, %2;" : "=f"(lo), "=f"(hi) : "l"(v));
}
__device__ __forceinline__ void ffma2(u64 &d, u64 a, u64 b) {
    asm("fma.rn.f32x2 %0, %1, %2, %0;" : "+l"(d) : "l"(a), "l"(b));
}

// Block: (b, i0) tile of 4 rows. 9 warps, warp = di.
// lane: il = lane>>3 (row 0..3), jseg = lane&7, thread owns 8 px (j0..j0+7),
// all 9 dj, full channels. One CTA wave (256 CTAs <= 296 slots at occ 2).
__global__ __launch_bounds__(288, 2)
void corr_kernel(const float* __restrict__ x,
                 const float* __restrict__ y,
                 float* __restrict__ out)
{
    __shared__ float smem[STAGES][BUFF];

    const int tid  = threadIdx.x;
    const int b    = blockIdx.x >> 4;
    const int i0   = (blockIdx.x & 15) * ITILE;
    const int di   = tid >> 5;
    const int lane = tid & 31;
    const int il   = lane >> 3;
    const int jseg = lane & 7;
    const int j0   = jseg * 8;
    const int i    = i0 + il;

    // ---- zero static y pads (units 0 and 17 of each row, all stages) ----
    for (int z = tid; z < STAGES * CC * YROWS * 8; z += 288) {
        int st  = z / (CC * YROWS * 8);
        int r1  = z - st * (CC * YROWS * 8);
        int ch  = r1 / (YROWS * 8);
        int r2  = r1 - ch * (YROWS * 8);
        int row = r2 >> 3;
        int p   = r2 & 7;
        int col = (p < 4) ? p : (64 + p);
        smem[st][XS + ch * YCH + row * YPITCH + col] = 0.f;
    }

    // ---- cp.async fill slots: 1024 = 160*4 + 128*3 ----
    const int nslot = (tid < 160) ? 4 : 3;
    uint32_t     s_off[4];
    const float* g_ptr[4];
    uint32_t     szbits = 0;          // bit s: slot s copies 16B (else zfill)
    {
        const float* xb = x + ((size_t)b * CHAN) * HW + (size_t)i0 * W;
        const float* yb = y + ((size_t)b * CHAN) * HW;
        #pragma unroll
        for (int s = 0; s < 4; s++) {
            int e = tid + s * 288;
            if (e >= NELEM) e = 0;                // dead slot (never issued)
            if (e < 256) {                        // x unit
                int ch = e >> 6, r = (e >> 4) & 3, u = e & 15;
                s_off[s] = (uint32_t)((ch * XCH + r * W + swz(u) * 4) * 4);
                g_ptr[s] = xb + ch * HW + r * W + u * 4;
                szbits |= 1u << s;
            } else {                              // y interior unit (1..16)
                int e2 = e - 256;
                int ch = e2 / 192, rem = e2 - ch * 192;
                int row = rem >> 4, ui = (rem & 15) + 1;
                int yr = i0 - MAXD + row;
                bool v = (yr >= 0) && (yr < H);
                s_off[s] = (uint32_t)((XS + ch * YCH + row * YPITCH + swz(ui) * 4) * 4);
                g_ptr[s] = yb + ch * HW + (v ? yr : 0) * W + (ui - 1) * 4;
                if (v) szbits |= 1u << s;
            }
        }
    }

    const uint32_t sm0 = (uint32_t)__cvta_generic_to_shared(&smem[0][0]);
    auto do_fill = [&](int st) {
        uint32_t base = sm0 + (uint32_t)st * (BUFF * 4);
        #pragma unroll
        for (int s = 0; s < 4; s++) {
            if (s < nslot) {
                uint32_t sz = ((szbits >> s) & 1u) ? 16u : 0u;
                asm volatile("cp.async.cg.shared.global [%0], [%1], 16, %2;"
                             :: "r"(base + s_off[s]), "l"(g_ptr[s]), "r"(sz));
                g_ptr[s] += CC * HW;
            }
        }
    };

    // ---- per-thread LDS base offsets (floats within stage buffer) ----
    const int xrow = il * W;                         // + ch*XCH
    const int yrow = XS + (il + di) * YPITCH;        // + ch*YCH

    // ---- accumulators: 32 u64 + 8 f32 = 72 regs ----
    u64 accE[5][4], accO[4][3];
    float aS0[4], aS7[4];
    #pragma unroll
    for (int e = 0; e < 5; e++)
        #pragma unroll
        for (int t = 0; t < 4; t++) accE[e][t] = 0ull;
    #pragma unroll
    for (int o = 0; o < 4; o++) {
        aS0[o] = 0.f; aS7[o] = 0.f;
        #pragma unroll
        for (int s = 0; s < 3; s++) accO[o][s] = 0ull;
    }

    __syncthreads();   // pads visible before first compute

    do_fill(0);
    asm volatile("cp.async.commit_group;" ::: "memory");
    do_fill(1);
    asm volatile("cp.async.commit_group;" ::: "memory");

    #pragma unroll 1
    for (int k = 0; k < NCHUNK; k++) {
        asm volatile("cp.async.wait_group 1;" ::: "memory");
        __syncthreads();   // publish stage k; all warps done with stage k-1
        if (k + 2 < NCHUNK) do_fill((k + 2) % STAGES);
        asm volatile("cp.async.commit_group;" ::: "memory");

        const float* B = &smem[k % STAGES][0];
        #pragma unroll
        for (int ch = 0; ch < CC; ch++) {
            const float* xs = B + ch * XCH + xrow;
            const float* ys = B + ch * YCH + yrow;
            float4 x0 = *reinterpret_cast<const float4*>(xs + swz(2 * jseg)     * 4);
            float4 x1 = *reinterpret_cast<const float4*>(xs + swz(2 * jseg + 1) * 4);
            float4 ya = *reinterpret_cast<const float4*>(ys + swz(2 * jseg)     * 4);
            float4 yb = *reinterpret_cast<const float4*>(ys + swz(2 * jseg + 1) * 4);
            float4 yc = *reinterpret_cast<const float4*>(ys + swz(2 * jseg + 2) * 4);
            float4 yd = *reinterpret_cast<const float4*>(ys + swz(2 * jseg + 3) * 4);

            u64 Pm[8] = { pack2(ya.x, ya.y), pack2(ya.z, ya.w),
                          pack2(yb.x, yb.y), pack2(yb.z, yb.w),
                          pack2(yc.x, yc.y), pack2(yc.z, yc.w),
                          pack2(yd.x, yd.y), pack2(yd.z, yd.w) };
            u64 XE[4] = { pack2(x0.x, x0.y), pack2(x0.z, x0.w),
                          pack2(x1.x, x1.y), pack2(x1.z, x1.w) };

            // even dj = 2e: px pair (2t,2t+1) x q-pair (t+e)
            #pragma unroll
            for (int e = 0; e < 5; e++)
                #pragma unroll
                for (int t = 0; t < 4; t++) ffma2(accE[e][t], XE[t], Pm[t + e]);

            u64 XO[3] = { pack2(x0.y, x0.z), pack2(x0.w, x1.x), pack2(x1.y, x1.z) };
            // odd dj = 2o+1: px pair (2s+1,2s+2) x q-pair (s+o+1)
            #pragma unroll
            for (int o = 0; o < 4; o++)
                #pragma unroll
                for (int s = 0; s < 3; s++) ffma2(accO[o][s], XO[s], Pm[s + o + 1]);
            // odd edges: px0 uses q[2o+1]; px7 uses q[2o+8]
            aS0[0] = fmaf(x0.x, ya.y, aS0[0]);
            aS0[1] = fmaf(x0.x, ya.w, aS0[1]);
            aS0[2] = fmaf(x0.x, yb.y, aS0[2]);
            aS0[3] = fmaf(x0.x, yb.w, aS0[3]);
            aS7[0] = fmaf(x1.w, yc.x, aS7[0]);
            aS7[1] = fmaf(x1.w, yc.z, aS7[1]);
            aS7[2] = fmaf(x1.w, yd.x, aS7[2]);
            aS7[3] = fmaf(x1.w, yd.z, aS7[3]);
        }
    }

    // ---- epilogue: scale by 1/C, two float4 stores per dj ----
    const float inv = 1.0f / (float)CHAN;
    float* ob = out + (((size_t)b * (PATCH * PATCH) + (size_t)di * PATCH) * H + i) * W + j0;
    #pragma unroll
    for (int dj = 0; dj < PATCH; dj++) {
        float v[8];
        if ((dj & 1) == 0) {
            const int e = dj >> 1;
            #pragma unroll
            for (int t = 0; t < 4; t++) unpack2(accE[e][t], v[2 * t], v[2 * t + 1]);
        } else {
            const int o = dj >> 1;
            v[0] = aS0[o];
            unpack2(accO[o][0], v[1], v[2]);
            unpack2(accO[o][1], v[3], v[4]);
            unpack2(accO[o][2], v[5], v[6]);
            v[7] = aS7[o];
        }
        float4 lo = make_float4(v[0] * inv, v[1] * inv, v[2] * inv, v[3] * inv);
        float4 hi = make_float4(v[4] * inv, v[5] * inv, v[6] * inv, v[7] * inv);
        *reinterpret_cast<float4*>(ob)     = lo;
        *reinterpret_cast<float4*>(ob + 4) = hi;
        ob += HW;
    }
}

extern "C" void kernel_launch(void* const* d_in, const int* in_sizes, int n_in,
                              void* d_out, int out_size)
{
    const float* x = (const float*)d_in[0];
    const float* y = (const float*)d_in[1];
    float* out = (float*)d_out;
    dim3 grid(BATCH * (H / ITILE));   // 256 blocks -> single wave at occ 2
    dim3 block(32 * PATCH);           // 288 threads = 9 warps
    corr_kernel<<<grid, block>>>(x, y, out);
}